// round 2
// baseline (speedup 1.0000x reference)
#include <cuda_runtime.h>
#include <cuda_bf16.h>

// Problem constants
#define BB 2
#define SS 2048
#define DD 1024
#define HH 16
#define HD 64
#define ROWS (BB*SS)          // 4096

// Scratch: projected Q/K/V in head-split layout [B, H, S, HD]
__device__ float g_Qp[BB*HH*SS*HD];
__device__ float g_Kp[BB*HH*SS*HD];
__device__ float g_Vp[BB*HH*SS*HD];

// ---------------------------------------------------------------------------
// Fused QKV projection: Y = X @ W + b, written head-split.
// Grid: (D/64, ROWS/64, 3), block 256. 64x64 tile, 4x4 per thread, k-tile 32.
// ---------------------------------------------------------------------------
__global__ void __launch_bounds__(256) qkv_proj_kernel(
    const float* __restrict__ q, const float* __restrict__ k, const float* __restrict__ v,
    const float* __restrict__ Wq, const float* __restrict__ bq,
    const float* __restrict__ Wk, const float* __restrict__ bk,
    const float* __restrict__ Wv, const float* __restrict__ bv)
{
    __shared__ float Xs[64][33];   // pitch 33: conflict-free column reads
    __shared__ float Ws[32][64];

    const float* X; const float* W; const float* bias; float* dst;
    if (blockIdx.z == 0)      { X = q; W = Wq; bias = bq; dst = g_Qp; }
    else if (blockIdx.z == 1) { X = k; W = Wk; bias = bk; dst = g_Kp; }
    else                      { X = v; W = Wv; bias = bv; dst = g_Vp; }

    const int tid = threadIdx.x;
    const int tx  = tid & 15;        // column group
    const int ty  = tid >> 4;        // row group
    const int row0 = blockIdx.y * 64;
    const int col0 = blockIdx.x * 64;

    // loader indices
    const int lm  = tid >> 2;        // 0..63   (X row)
    const int lk0 = (tid & 3) * 8;   // 0,8,16,24 (X k-chunk, 8 floats)
    const int lkw = tid >> 3;        // 0..31   (W k-row)
    const int ln0 = (tid & 7) * 8;   // 0..56   (W col chunk, 8 floats)

    float acc[4][4] = {};

    for (int k0 = 0; k0 < DD; k0 += 32) {
        __syncthreads();
        {
            float4 x0 = *(const float4*)(X + (row0 + lm) * DD + k0 + lk0);
            float4 x1 = *(const float4*)(X + (row0 + lm) * DD + k0 + lk0 + 4);
            Xs[lm][lk0 + 0] = x0.x; Xs[lm][lk0 + 1] = x0.y;
            Xs[lm][lk0 + 2] = x0.z; Xs[lm][lk0 + 3] = x0.w;
            Xs[lm][lk0 + 4] = x1.x; Xs[lm][lk0 + 5] = x1.y;
            Xs[lm][lk0 + 6] = x1.z; Xs[lm][lk0 + 7] = x1.w;
            float4 w0 = *(const float4*)(W + (k0 + lkw) * DD + col0 + ln0);
            float4 w1 = *(const float4*)(W + (k0 + lkw) * DD + col0 + ln0 + 4);
            *(float4*)&Ws[lkw][ln0]     = w0;
            *(float4*)&Ws[lkw][ln0 + 4] = w1;
        }
        __syncthreads();

        #pragma unroll
        for (int kk = 0; kk < 32; kk++) {
            float xr[4], wr[4];
            #pragma unroll
            for (int i = 0; i < 4; i++) xr[i] = Xs[ty + 16 * i][kk];
            #pragma unroll
            for (int j = 0; j < 4; j++) wr[j] = Ws[kk][tx + 16 * j];
            #pragma unroll
            for (int i = 0; i < 4; i++)
                #pragma unroll
                for (int j = 0; j < 4; j++)
                    acc[i][j] += xr[i] * wr[j];
        }
    }

    // Epilogue: bias + head-split store  dst[((b*H + h)*S + s)*HD + hd]
    #pragma unroll
    for (int j = 0; j < 4; j++) {
        const int e  = col0 + tx + 16 * j;     // output feature
        const int h  = e >> 6;
        const int hd = e & 63;
        const float bv_ = bias[e];
        #pragma unroll
        for (int i = 0; i < 4; i++) {
            const int row = row0 + ty + 16 * i;   // b*S + s
            const int bb  = row >> 11;            // /2048
            const int s   = row & 2047;
            dst[(((bb * HH + h) * SS) + s) * HD + hd] = acc[i][j] + bv_;
        }
    }
}

// ---------------------------------------------------------------------------
// Flash attention: one block = 64 queries of one (b,h). Online softmax.
// Grid: (S/64, H, B), block 256.  Dynamic smem: Q[64][64], K[64][65], V[64][64]
// K buffer is reused to hold P for the PV GEMM.
// ---------------------------------------------------------------------------
#define ATTN_SMEM_FLOATS (64*64 + 64*65 + 64*64)
#define ATTN_SMEM_BYTES  (ATTN_SMEM_FLOATS * 4)

__global__ void __launch_bounds__(256) attn_kernel(float* __restrict__ out)
{
    extern __shared__ float sm[];
    float* Qs = sm;                 // pitch 64
    float* Ks = sm + 64 * 64;       // pitch 65 (conflict-free QK^T reads)
    float* Vs = Ks + 64 * 65;       // pitch 64

    const int tid = threadIdx.x;
    const int tx  = tid & 15;
    const int ty  = tid >> 4;
    const int qt  = blockIdx.x;
    const int h   = blockIdx.y;
    const int b   = blockIdx.z;

    const float* Qbase = g_Qp + ((b * HH + h) * SS + qt * 64) * HD;
    const float* Kbase = g_Kp + ((b * HH + h) * SS) * HD;
    const float* Vbase = g_Vp + ((b * HH + h) * SS) * HD;

    // loader indices: each thread loads one row-quarter (16 floats = 4 float4)
    const int lm  = tid >> 2;          // 0..63
    const int lh0 = (tid & 3) * 16;    // 0,16,32,48

    // Load Q tile once
    {
        const float4* src = (const float4*)(Qbase + lm * HD + lh0);
        float4* dq = (float4*)(Qs + lm * 64 + lh0);
        dq[0] = src[0]; dq[1] = src[1]; dq[2] = src[2]; dq[3] = src[3];
    }

    float m_i[4], l_i[4], Oa[4][4];
    #pragma unroll
    for (int i = 0; i < 4; i++) {
        m_i[i] = -1e30f; l_i[i] = 0.f;
        #pragma unroll
        for (int j = 0; j < 4; j++) Oa[i][j] = 0.f;
    }

    const float scale = 0.125f;  // 1/sqrt(64)

    for (int kt = 0; kt < SS / 64; kt++) {
        __syncthreads();  // prior PV done reading Ks/Vs; makes Q visible on iter 0
        // Load K (scalar stores: pitch 65) and V (float4: pitch 64)
        {
            const float4* ks = (const float4*)(Kbase + (kt * 64 + lm) * HD + lh0);
            float4 k0 = ks[0], k1 = ks[1], k2 = ks[2], k3 = ks[3];
            float* kd = Ks + lm * 65 + lh0;
            kd[0]=k0.x; kd[1]=k0.y; kd[2]=k0.z; kd[3]=k0.w;
            kd[4]=k1.x; kd[5]=k1.y; kd[6]=k1.z; kd[7]=k1.w;
            kd[8]=k2.x; kd[9]=k2.y; kd[10]=k2.z; kd[11]=k2.w;
            kd[12]=k3.x; kd[13]=k3.y; kd[14]=k3.z; kd[15]=k3.w;
            const float4* vs = (const float4*)(Vbase + (kt * 64 + lm) * HD + lh0);
            float4* vd = (float4*)(Vs + lm * 64 + lh0);
            vd[0] = vs[0]; vd[1] = vs[1]; vd[2] = vs[2]; vd[3] = vs[3];
        }
        __syncthreads();

        // S = Q @ K^T  (4x4 per thread)
        float Sv[4][4] = {};
        #pragma unroll 8
        for (int hd = 0; hd < 64; hd++) {
            float qv[4], kv[4];
            #pragma unroll
            for (int i = 0; i < 4; i++) qv[i] = Qs[(ty + 16 * i) * 64 + hd];
            #pragma unroll
            for (int j = 0; j < 4; j++) kv[j] = Ks[(tx + 16 * j) * 65 + hd];
            #pragma unroll
            for (int i = 0; i < 4; i++)
                #pragma unroll
                for (int j = 0; j < 4; j++)
                    Sv[i][j] += qv[i] * kv[j];
        }

        // Online softmax update
        float P[4][4];
        float alpha[4], rsum[4];
        #pragma unroll
        for (int i = 0; i < 4; i++) {
            float tmax = -1e30f;
            #pragma unroll
            for (int j = 0; j < 4; j++) { Sv[i][j] *= scale; tmax = fmaxf(tmax, Sv[i][j]); }
            #pragma unroll
            for (int off = 8; off >= 1; off >>= 1)
                tmax = fmaxf(tmax, __shfl_xor_sync(0xffffffffu, tmax, off));
            const float mnew = fmaxf(m_i[i], tmax);
            alpha[i] = __expf(m_i[i] - mnew);
            m_i[i] = mnew;
            float rs = 0.f;
            #pragma unroll
            for (int j = 0; j < 4; j++) { P[i][j] = __expf(Sv[i][j] - mnew); rs += P[i][j]; }
            #pragma unroll
            for (int off = 8; off >= 1; off >>= 1)
                rs += __shfl_xor_sync(0xffffffffu, rs, off);
            rsum[i] = rs;
        }
        #pragma unroll
        for (int i = 0; i < 4; i++) {
            l_i[i] = l_i[i] * alpha[i] + rsum[i];
            #pragma unroll
            for (int j = 0; j < 4; j++) Oa[i][j] *= alpha[i];
        }

        __syncthreads();  // everyone done reading Ks
        // Store P into the K buffer (pitch 65)
        #pragma unroll
        for (int i = 0; i < 4; i++)
            #pragma unroll
            for (int j = 0; j < 4; j++)
                Ks[(ty + 16 * i) * 65 + tx + 16 * j] = P[i][j];
        __syncthreads();

        // O += P @ V
        #pragma unroll 8
        for (int kk = 0; kk < 64; kk++) {
            float pv[4], vv[4];
            #pragma unroll
            for (int i = 0; i < 4; i++) pv[i] = Ks[(ty + 16 * i) * 65 + kk];
            #pragma unroll
            for (int j = 0; j < 4; j++) vv[j] = Vs[kk * 64 + tx + 16 * j];
            #pragma unroll
            for (int i = 0; i < 4; i++)
                #pragma unroll
                for (int j = 0; j < 4; j++)
                    Oa[i][j] += pv[i] * vv[j];
        }
    }

    // Epilogue: normalize and write merged-head output [B, S, D]
    #pragma unroll
    for (int i = 0; i < 4; i++) {
        const float inv = 1.0f / l_i[i];
        const int s = qt * 64 + ty + 16 * i;
        #pragma unroll
        for (int j = 0; j < 4; j++) {
            const int c = tx + 16 * j;
            out[(b * SS + s) * DD + h * HD + c] = Oa[i][j] * inv;
        }
    }
}

// ---------------------------------------------------------------------------
extern "C" void kernel_launch(void* const* d_in, const int* in_sizes, int n_in,
                              void* d_out, int out_size)
{
    const float* q  = (const float*)d_in[0];
    const float* k  = (const float*)d_in[1];
    const float* v  = (const float*)d_in[2];
    const float* Wq = (const float*)d_in[3];
    const float* bq = (const float*)d_in[4];
    const float* Wk = (const float*)d_in[5];
    const float* bk = (const float*)d_in[6];
    const float* Wv = (const float*)d_in[7];
    const float* bv = (const float*)d_in[8];
    float* out = (float*)d_out;

    dim3 gp(DD / 64, ROWS / 64, 3);
    qkv_proj_kernel<<<gp, 256>>>(q, k, v, Wq, bq, Wk, bk, Wv, bv);

    static int smem_set = 0;
    if (!smem_set) {
        cudaFuncSetAttribute(attn_kernel, cudaFuncAttributeMaxDynamicSharedMemorySize,
                             ATTN_SMEM_BYTES);
        smem_set = 1;
    }
    dim3 ga(SS / 64, HH, BB);
    attn_kernel<<<ga, 256, ATTN_SMEM_BYTES>>>(out);
}

// round 3
// speedup vs baseline: 4.0501x; 4.0501x over previous
#include <cuda_runtime.h>
#include <cstdint>

// Problem constants
#define BB 2
#define SS 2048
#define DD 1024
#define HH 16
#define HD 64

// Scratch: projected Q/K/V in head-split layout [B, H, S, HD]
__device__ float g_Qp[BB*HH*SS*HD];
__device__ float g_Kp[BB*HH*SS*HD];
__device__ float g_Vp[BB*HH*SS*HD];

// ---------------------------------------------------------------------------
// tf32 helpers
// ---------------------------------------------------------------------------
__device__ __forceinline__ uint32_t f2tf32(float x) {
    uint32_t r;
    asm("cvt.rna.tf32.f32 %0, %1;" : "=r"(r) : "f"(x));
    return r;
}

// D += A * B, m16n8k8, A row-major, B col-major (B[k][n] indexed as (row=k,col=n))
__device__ __forceinline__ void mma_tf32(float* c,
                                         uint32_t a0, uint32_t a1, uint32_t a2, uint32_t a3,
                                         uint32_t b0, uint32_t b1) {
    asm volatile("mma.sync.aligned.m16n8k8.row.col.f32.tf32.tf32.f32 "
                 "{%0,%1,%2,%3}, {%4,%5,%6,%7}, {%8,%9}, {%0,%1,%2,%3};"
                 : "+f"(c[0]), "+f"(c[1]), "+f"(c[2]), "+f"(c[3])
                 : "r"(a0), "r"(a1), "r"(a2), "r"(a3), "r"(b0), "r"(b1));
}

// ---------------------------------------------------------------------------
// QKV projection, tf32 tensor cores.
// Block tile 128(m) x 128(n), k-tile 32, 256 threads = 8 warps (4m x 2n),
// warp tile 32x64. Grid: (DD/128, ROWS/128, 3).
// ---------------------------------------------------------------------------
#define PJ_THREADS 256
#define XP 36    // Xs pitch (uint32): bank = 4g + c  -> conflict-free frag loads
#define WP 136   // Ws pitch: bank = 8c + g           -> conflict-free frag loads

__global__ void __launch_bounds__(PJ_THREADS) qkv_proj_mma(
    const float* __restrict__ q, const float* __restrict__ k, const float* __restrict__ v,
    const float* __restrict__ Wq, const float* __restrict__ bq,
    const float* __restrict__ Wk, const float* __restrict__ bk,
    const float* __restrict__ Wv, const float* __restrict__ bv)
{
    __shared__ uint32_t Xs[128 * XP];   // 18432 B
    __shared__ uint32_t Ws[32 * WP];    // 17408 B

    const float* X; const float* W; const float* bias; float* dst;
    if (blockIdx.z == 0)      { X = q; W = Wq; bias = bq; dst = g_Qp; }
    else if (blockIdx.z == 1) { X = k; W = Wk; bias = bk; dst = g_Kp; }
    else                      { X = v; W = Wv; bias = bv; dst = g_Vp; }

    const int tid  = threadIdx.x;
    const int lane = tid & 31, wid = tid >> 5;
    const int g = lane >> 2, c = lane & 3;
    const int wm = wid >> 1, wn = wid & 1;
    const int row0 = blockIdx.y * 128, col0 = blockIdx.x * 128;

    float acc[2][8][4] = {};

    for (int kt = 0; kt < DD; kt += 32) {
        __syncthreads();
        // X tile 128x32 (4 float4 per thread)
        #pragma unroll
        for (int i = 0; i < 4; i++) {
            int idx = tid + PJ_THREADS * i;      // 0..1023
            int r = idx >> 3, c4 = idx & 7;
            float4 xv = *(const float4*)(X + (row0 + r) * DD + kt + c4 * 4);
            uint4 uv; uv.x = f2tf32(xv.x); uv.y = f2tf32(xv.y);
                      uv.z = f2tf32(xv.z); uv.w = f2tf32(xv.w);
            *(uint4*)&Xs[r * XP + c4 * 4] = uv;
        }
        // W tile 32x128
        #pragma unroll
        for (int i = 0; i < 4; i++) {
            int idx = tid + PJ_THREADS * i;
            int r = idx >> 5, c4 = idx & 31;
            float4 wv = *(const float4*)(W + (kt + r) * DD + col0 + c4 * 4);
            uint4 uv; uv.x = f2tf32(wv.x); uv.y = f2tf32(wv.y);
                      uv.z = f2tf32(wv.z); uv.w = f2tf32(wv.w);
            *(uint4*)&Ws[r * WP + c4 * 4] = uv;
        }
        __syncthreads();

        #pragma unroll
        for (int kk = 0; kk < 4; kk++) {
            uint32_t A[2][4];
            #pragma unroll
            for (int mt = 0; mt < 2; mt++) {
                int rb = wm * 32 + mt * 16 + g;
                A[mt][0] = Xs[rb * XP + kk * 8 + c];
                A[mt][1] = Xs[(rb + 8) * XP + kk * 8 + c];
                A[mt][2] = Xs[rb * XP + kk * 8 + c + 4];
                A[mt][3] = Xs[(rb + 8) * XP + kk * 8 + c + 4];
            }
            #pragma unroll
            for (int nt = 0; nt < 8; nt++) {
                int nb = wn * 64 + nt * 8 + g;
                uint32_t b0 = Ws[(kk * 8 + c) * WP + nb];
                uint32_t b1 = Ws[(kk * 8 + c + 4) * WP + nb];
                mma_tf32(acc[0][nt], A[0][0], A[0][1], A[0][2], A[0][3], b0, b1);
                mma_tf32(acc[1][nt], A[1][0], A[1][1], A[1][2], A[1][3], b0, b1);
            }
        }
    }

    // Epilogue: bias + head-split scatter. C frag cols 2c,2c+1 -> float2.
    #pragma unroll
    for (int nt = 0; nt < 8; nt++) {
        const int e  = col0 + wn * 64 + nt * 8 + 2 * c;  // even
        const int hh = e >> 6;
        const int hd = e & 63;
        const float bv0 = bias[e], bv1 = bias[e + 1];
        #pragma unroll
        for (int mt = 0; mt < 2; mt++) {
            int r = row0 + wm * 32 + mt * 16 + g;
            int bb = r >> 11, s = r & 2047;
            float2 o0; o0.x = acc[mt][nt][0] + bv0; o0.y = acc[mt][nt][1] + bv1;
            *(float2*)&dst[(((bb * HH + hh) * SS) + s) * HD + hd] = o0;
            int r2 = r + 8;
            int bb2 = r2 >> 11, s2 = r2 & 2047;
            float2 o1; o1.x = acc[mt][nt][2] + bv0; o1.y = acc[mt][nt][3] + bv1;
            *(float2*)&dst[(((bb2 * HH + hh) * SS) + s2) * HD + hd] = o1;
        }
    }
}

// ---------------------------------------------------------------------------
// Flash attention, tf32 tensor cores. Block = 64 queries x full keys of one
// (b,h). 128 threads = 4 warps, warp = 16 query rows. Key tile 64.
// K and V consumed as B fragments straight from their natural [row][hd]
// layout; P converted C-frag -> A-frag via quad shuffles (no smem, no sync).
// ---------------------------------------------------------------------------
#define AT_THREADS 128
#define QKP 68   // Q/K pitch: bank = 4g + c -> conflict-free
#define VP  72   // V pitch:   bank = 8c + g -> conflict-free
#define AT_SMEM ((64*QKP + 64*QKP + 64*VP) * 4)   // 53248 B

__global__ void __launch_bounds__(AT_THREADS) attn_mma(float* __restrict__ out)
{
    extern __shared__ uint32_t sm[];
    uint32_t* Qs = sm;
    uint32_t* Ks = sm + 64 * QKP;
    uint32_t* Vs = Ks + 64 * QKP;

    const int tid  = threadIdx.x;
    const int lane = tid & 31, wid = tid >> 5;
    const int g = lane >> 2, c = lane & 3;
    const int qt = blockIdx.x, h = blockIdx.y, b = blockIdx.z;

    const float* Qbase = g_Qp + ((b * HH + h) * SS + qt * 64) * HD;
    const float* Kbase = g_Kp + ((b * HH + h) * SS) * HD;
    const float* Vbase = g_Vp + ((b * HH + h) * SS) * HD;

    // Load Q tile once (8 float4 per thread), tf32-converted
    #pragma unroll
    for (int i = 0; i < 8; i++) {
        int idx = tid + AT_THREADS * i;
        int r = idx >> 4, c4 = idx & 15;
        float4 qv = *(const float4*)(Qbase + r * HD + c4 * 4);
        uint4 uv; uv.x = f2tf32(qv.x); uv.y = f2tf32(qv.y);
                  uv.z = f2tf32(qv.z); uv.w = f2tf32(qv.w);
        *(uint4*)&Qs[r * QKP + c4 * 4] = uv;
    }

    float Oa[8][4] = {};
    float m0 = -1e30f, m1 = -1e30f, l0 = 0.f, l1 = 0.f;
    const float scale = 0.125f;   // 1/sqrt(64)
    const int qrow = wid * 16 + g;

    for (int kt = 0; kt < SS / 64; kt++) {
        __syncthreads();  // prior iteration done reading Ks/Vs (and Q visible)
        const float* Kt = Kbase + kt * 64 * HD;
        const float* Vt = Vbase + kt * 64 * HD;
        #pragma unroll
        for (int i = 0; i < 8; i++) {
            int idx = tid + AT_THREADS * i;
            int r = idx >> 4, c4 = idx & 15;
            float4 kv = *(const float4*)(Kt + r * HD + c4 * 4);
            uint4 ku; ku.x = f2tf32(kv.x); ku.y = f2tf32(kv.y);
                      ku.z = f2tf32(kv.z); ku.w = f2tf32(kv.w);
            *(uint4*)&Ks[r * QKP + c4 * 4] = ku;
            float4 vv = *(const float4*)(Vt + r * HD + c4 * 4);
            uint4 vu; vu.x = f2tf32(vv.x); vu.y = f2tf32(vv.y);
                      vu.z = f2tf32(vv.z); vu.w = f2tf32(vv.w);
            *(uint4*)&Vs[r * VP + c4 * 4] = vu;
        }
        __syncthreads();

        // ---- S = Q K^T : 8 k-steps (hd) x 8 n-tiles (keys) ----
        float S[8][4] = {};
        #pragma unroll
        for (int kk = 0; kk < 8; kk++) {
            uint32_t a0 = Qs[qrow * QKP + kk * 8 + c];
            uint32_t a1 = Qs[(qrow + 8) * QKP + kk * 8 + c];
            uint32_t a2 = Qs[qrow * QKP + kk * 8 + c + 4];
            uint32_t a3 = Qs[(qrow + 8) * QKP + kk * 8 + c + 4];
            #pragma unroll
            for (int nt = 0; nt < 8; nt++) {
                uint32_t b0 = Ks[(nt * 8 + g) * QKP + kk * 8 + c];
                uint32_t b1 = Ks[(nt * 8 + g) * QKP + kk * 8 + c + 4];
                mma_tf32(S[nt], a0, a1, a2, a3, b0, b1);
            }
        }

        // ---- online softmax (row r0=qrow uses S[][0,1]; r1=qrow+8 uses S[][2,3]) ----
        float mx0 = -1e30f, mx1 = -1e30f;
        #pragma unroll
        for (int nt = 0; nt < 8; nt++) {
            #pragma unroll
            for (int u = 0; u < 4; u++) S[nt][u] *= scale;
            mx0 = fmaxf(mx0, fmaxf(S[nt][0], S[nt][1]));
            mx1 = fmaxf(mx1, fmaxf(S[nt][2], S[nt][3]));
        }
        mx0 = fmaxf(mx0, __shfl_xor_sync(0xffffffffu, mx0, 1));
        mx0 = fmaxf(mx0, __shfl_xor_sync(0xffffffffu, mx0, 2));
        mx1 = fmaxf(mx1, __shfl_xor_sync(0xffffffffu, mx1, 1));
        mx1 = fmaxf(mx1, __shfl_xor_sync(0xffffffffu, mx1, 2));
        const float mn0 = fmaxf(m0, mx0), mn1 = fmaxf(m1, mx1);
        const float al0 = __expf(m0 - mn0), al1 = __expf(m1 - mn1);
        m0 = mn0; m1 = mn1;
        float s0 = 0.f, s1 = 0.f;
        #pragma unroll
        for (int nt = 0; nt < 8; nt++) {
            S[nt][0] = __expf(S[nt][0] - mn0);
            S[nt][1] = __expf(S[nt][1] - mn0);
            S[nt][2] = __expf(S[nt][2] - mn1);
            S[nt][3] = __expf(S[nt][3] - mn1);
            s0 += S[nt][0] + S[nt][1];
            s1 += S[nt][2] + S[nt][3];
        }
        s0 += __shfl_xor_sync(0xffffffffu, s0, 1);
        s0 += __shfl_xor_sync(0xffffffffu, s0, 2);
        s1 += __shfl_xor_sync(0xffffffffu, s1, 1);
        s1 += __shfl_xor_sync(0xffffffffu, s1, 2);
        l0 = l0 * al0 + s0;
        l1 = l1 * al1 + s1;
        #pragma unroll
        for (int nt = 0; nt < 8; nt++) {
            Oa[nt][0] *= al0; Oa[nt][1] *= al0;
            Oa[nt][2] *= al1; Oa[nt][3] *= al1;
        }

        // ---- O += P V : per k-tile j (8 keys), A-frag via quad shuffles ----
        const int base = lane & 28;
        const int L0 = base | (c >> 1);
        const int L1 = L0 | 2;
        const bool hi = (c & 1) != 0;
        #pragma unroll
        for (int j = 0; j < 8; j++) {
            float p00 = __shfl_sync(0xffffffffu, S[j][0], L0);
            float p01 = __shfl_sync(0xffffffffu, S[j][1], L0);
            float p10 = __shfl_sync(0xffffffffu, S[j][2], L0);
            float p11 = __shfl_sync(0xffffffffu, S[j][3], L0);
            float q00 = __shfl_sync(0xffffffffu, S[j][0], L1);
            float q01 = __shfl_sync(0xffffffffu, S[j][1], L1);
            float q10 = __shfl_sync(0xffffffffu, S[j][2], L1);
            float q11 = __shfl_sync(0xffffffffu, S[j][3], L1);
            uint32_t a0 = f2tf32(hi ? p01 : p00);   // P[r0][8j+c]
            uint32_t a1 = f2tf32(hi ? p11 : p10);   // P[r1][8j+c]
            uint32_t a2 = f2tf32(hi ? q01 : q00);   // P[r0][8j+c+4]
            uint32_t a3 = f2tf32(hi ? q11 : q10);   // P[r1][8j+c+4]
            #pragma unroll
            for (int nt = 0; nt < 8; nt++) {
                uint32_t b0 = Vs[(j * 8 + c) * VP + nt * 8 + g];
                uint32_t b1 = Vs[(j * 8 + c + 4) * VP + nt * 8 + g];
                mma_tf32(Oa[nt], a0, a1, a2, a3, b0, b1);
            }
        }
    }

    // ---- epilogue: normalize, merged-head store [B, S, D] ----
    const float inv0 = 1.0f / l0, inv1 = 1.0f / l1;
    const int s = qt * 64 + qrow;
    #pragma unroll
    for (int nt = 0; nt < 8; nt++) {
        const int col = h * HD + nt * 8 + 2 * c;
        float2 o0; o0.x = Oa[nt][0] * inv0; o0.y = Oa[nt][1] * inv0;
        *(float2*)&out[(b * SS + s) * DD + col] = o0;
        float2 o1; o1.x = Oa[nt][2] * inv1; o1.y = Oa[nt][3] * inv1;
        *(float2*)&out[(b * SS + s + 8) * DD + col] = o1;
    }
}

// ---------------------------------------------------------------------------
extern "C" void kernel_launch(void* const* d_in, const int* in_sizes, int n_in,
                              void* d_out, int out_size)
{
    const float* q  = (const float*)d_in[0];
    const float* k  = (const float*)d_in[1];
    const float* v  = (const float*)d_in[2];
    const float* Wq = (const float*)d_in[3];
    const float* bq = (const float*)d_in[4];
    const float* Wk = (const float*)d_in[5];
    const float* bk = (const float*)d_in[6];
    const float* Wv = (const float*)d_in[7];
    const float* bv = (const float*)d_in[8];
    float* out = (float*)d_out;

    dim3 gp(DD / 128, (BB * SS) / 128, 3);
    qkv_proj_mma<<<gp, PJ_THREADS>>>(q, k, v, Wq, bq, Wk, bk, Wv, bv);

    static int smem_set = 0;
    if (!smem_set) {
        cudaFuncSetAttribute(attn_mma, cudaFuncAttributeMaxDynamicSharedMemorySize,
                             AT_SMEM);
        smem_set = 1;
    }
    dim3 ga(SS / 64, HH, BB);
    attn_mma<<<ga, AT_THREADS, AT_SMEM>>>(out);
}